// round 17
// baseline (speedup 1.0000x reference)
#include <cuda_runtime.h>
#include <math.h>
#include <stdint.h>

// out = LayerNorm(Re(FFT(x, axis=-1))), x: (4,4096,2048) fp32.
// Pack z[n] = x[2n] + i x[2n+1] (1024 complex). 4-step CT: 1024 = 32 x 32,
// one WARP per row, 32 complex per lane:
//   FFT32 (regs, packed f32x2 add/sub) -> twiddle W_1024^{u k1} (register
//   recurrence) -> float2 smem transpose (pad 33, phase-conflict-free)
//   -> FFT32: r[i] = Z[u+32*brev5(i)]
// Paired untangle over kk=0..15 (k = u+32kk in [0,512)), uk05 = 0.5*U[k]:
//   (S,T) = Zk + conj-pair, D = Zk.x - zmx
//   y[k] = 0.5 S + uk05.x T + uk05.y D;  y[1024-k] = S - y[k]
//   (y1, S) overwrite dead register r[brev5(kk)] (even regs only; odd regs,
//   incl. r[1] = Z[512], survive). ssq via packed fma2 accumulator.
//   kk=0 pair IS y[1024]; y[512] = r[1].x on lane 0. mu = x[0] exactly.
// No tables, no __syncthreads; warps fully independent.

#define ROWS 16384
#define CDIM 2048
#define EPS  1e-5f
#define FULL 0xffffffffu

__device__ __forceinline__ float2 cmul(float2 a, float2 b) {
    return make_float2(fmaf(a.x, b.x, -a.y * b.y), fmaf(a.x, b.y, a.y * b.x));
}
__device__ __forceinline__ float2 fadd2(float2 a, float2 b) {
    unsigned long long ra, rb, rc;
    ra = *(unsigned long long*)&a;
    rb = *(unsigned long long*)&b;
    asm("add.rn.f32x2 %0, %1, %2;" : "=l"(rc) : "l"(ra), "l"(rb));
    return *(float2*)&rc;
}
__device__ __forceinline__ float2 fsub2(float2 a, float2 b) {
    unsigned long long ra, rb, rc;
    ra = *(unsigned long long*)&a;
    rb = *(unsigned long long*)&b;
    asm("sub.rn.f32x2 %0, %1, %2;" : "=l"(rc) : "l"(ra), "l"(rb));
    return *(float2*)&rc;
}
__device__ __forceinline__ float2 ffma2(float2 a, float2 b, float2 c) {
    unsigned long long ra, rb, rc, rd;
    ra = *(unsigned long long*)&a;
    rb = *(unsigned long long*)&b;
    rc = *(unsigned long long*)&c;
    asm("fma.rn.f32x2 %0, %1, %2, %3;" : "=l"(rd) : "l"(ra), "l"(rb), "l"(rc));
    return *(float2*)&rd;
}

__host__ __device__ constexpr int brev5(int i) {
    return ((i & 1) << 4) | ((i & 2) << 2) | (i & 4) | ((i & 8) >> 2) | ((i & 16) >> 4);
}

// 32-pt DIF FFT (Gentleman-Sande), output bit-reversed: r[i] = X[brev5(i)].
__device__ __forceinline__ void fft32(float2* r) {
    const float CR[16] = { 1.0f, 0.98078528f, 0.92387953f, 0.83146961f,
                           0.70710678f, 0.55557023f, 0.38268343f, 0.19509032f,
                           0.0f, -0.19509032f, -0.38268343f, -0.55557023f,
                           -0.70710678f, -0.83146961f, -0.92387953f, -0.98078528f };
    const float CI[16] = { 0.0f, -0.19509032f, -0.38268343f, -0.55557023f,
                           -0.70710678f, -0.83146961f, -0.92387953f, -0.98078528f,
                           -1.0f, -0.98078528f, -0.92387953f, -0.83146961f,
                           -0.70710678f, -0.55557023f, -0.38268343f, -0.19509032f };
    #pragma unroll
    for (int half = 16; half >= 1; half >>= 1) {
        #pragma unroll
        for (int g = 0; g < 32; g += 2 * half) {
            #pragma unroll
            for (int j = 0; j < half; j++) {
                float2 a = r[g + j], b = r[g + j + half];
                r[g + j] = fadd2(a, b);
                float2 d = fsub2(a, b);
                int tw = j * (16 / half);
                if (tw == 0) r[g + j + half] = d;
                else r[g + j + half] = make_float2(fmaf(d.x, CR[tw], -d.y * CI[tw]),
                                                   fmaf(d.x, CI[tw],  d.y * CR[tw]));
            }
        }
    }
}

__global__ void __launch_bounds__(128, 4) fft_ln_kernel(const float* __restrict__ x,
                                                        const float* __restrict__ gamma,
                                                        const float* __restrict__ beta,
                                                        float* __restrict__ out) {
    __shared__ float2 Sc[4][33 * 32];

    const int t = threadIdx.x;
    const int w = t >> 5;
    const int u = t & 31;
    const int row = blockIdx.x * 4 + w;
    const float2* z = (const float2*)(x + (size_t)row * CDIM);

    float2 r[32];
    #pragma unroll
    for (int j = 0; j < 32; j++) r[j] = z[u + 32 * j];
    const float mu = __shfl_sync(FULL, r[0].x, 0);

    // ---- first FFT
    fft32(r);

    // ---- twiddle r[brev5(c)] *= W_1024^{u*c}; wstep = exp(-i pi u/512)
    {
        float s, c;
        sincospif((float)u * (1.0f / 512.0f), &s, &c);
        float2 wstep = make_float2(c, -s);
        float2 w2 = cmul(wstep, wstep);
        float2 w4 = cmul(w2, w2);
        float2 w8 = cmul(w4, w4);
        float2 w16 = cmul(w8, w8);
        float2 base[4] = { make_float2(1.0f, 0.0f), w8, w16, cmul(w16, w8) };
        #pragma unroll
        for (int q = 0; q < 4; q++) {
            float2 wc = base[q];
            #pragma unroll
            for (int j = 0; j < 8; j++) {
                int c2 = 8 * q + j;
                if (c2 != 0) r[brev5(c2)] = cmul(r[brev5(c2)], wc);
                wc = cmul(wc, wstep);
            }
        }
    }

    // ---- transpose (float2, pad 33): lane u=n2 -> lane u=k1
    float2* sc = Sc[w];
    #pragma unroll
    for (int i = 0; i < 32; i++) sc[brev5(i) * 33 + u] = r[i];
    __syncwarp();
    #pragma unroll
    for (int j = 0; j < 32; j++) r[j] = sc[u * 33 + j];
    __syncwarp();

    // ---- second FFT: r[i] = Z[u + 32*brev5(i)]
    fft32(r);

    // ---- paired untangle; (y1, S) overwrite dead (even) register r[i]
    const int pux = (32 - u) & 31;
    float2 sq2 = make_float2(0.0f, 0.0f);
    float y0v = 0.0f, y1024v = 0.0f;
    float2 uk;
    {
        float s, c;
        sincospif((float)u * (1.0f / 1024.0f), &s, &c);
        uk = make_float2(0.5f * c, -0.5f * s);       // 0.5 * U[u]
    }
    const float2 W32 = make_float2(0.99518473f, -0.09801714f);  // exp(-i pi/32)
    #pragma unroll
    for (int kk = 0; kk < 16; kk++) {
        const int i = brev5(kk);                     // even for kk < 16
        float2 Zk = r[i];
        float zmx = __shfl_sync(FULL, r[31 - i].x, pux);
        float zmy = __shfl_sync(FULL, r[31 - i].y, pux);
        if (u == 0) {
            int i0 = brev5((32 - kk) & 31);          // kk=0 -> 0 (pre-write); else odd
            zmx = r[i0].x;
            zmy = r[i0].y;
        }
        float2 ST = fadd2(Zk, make_float2(zmx, zmy));   // (S, T)
        float D = Zk.x - zmx;
        float y1 = fmaf(uk.x, ST.y, fmaf(uk.y, D, 0.5f * ST.x));  // y[k]
        float y2 = ST.x - y1;                        // y[1024-k]
        r[i] = make_float2(y1, ST.x);                // stage (y1, S)
        float2 yy = make_float2(y1, y2);
        sq2 = ffma2(yy, yy, sq2);
        if (kk == 0 && u == 0) { y0v = y1; y1024v = y2; }
        uk = cmul(uk, W32);
    }
    float sloc = sq2.x + sq2.y;
    if (u == 0) {
        float y512 = r[1].x;                         // Z[512] real; odd reg intact
        sloc += y512 * y512 - 0.5f * (y0v * y0v + y1024v * y1024v);
    }

    #pragma unroll
    for (int o = 16; o > 0; o >>= 1) sloc += __shfl_xor_sync(FULL, sloc, o);
    const float rs = rsqrtf(sloc * (1.0f / 1024.0f) - mu * mu + EPS);
    const float cc = -mu * rs;

    // ---- scaled stores: 4 mirrored regions per kk, register-only rescan
    float* orow = out + (size_t)row * CDIM;
    #pragma unroll
    for (int kk = 0; kk < 16; kk++) {
        const int i = brev5(kk);
        float y1 = r[i].x;
        float y2 = r[i].y - y1;                      // S - y1
        int k = u + (kk << 5);
        float zn1 = fmaf(y1, rs, cc);
        float zn2 = fmaf(y2, rs, cc);
        orow[k] = fmaf(zn1, __ldg(gamma + k), __ldg(beta + k));
        if (k > 0)
            orow[2048 - k] = fmaf(zn1, __ldg(gamma + 2048 - k), __ldg(beta + 2048 - k));
        orow[1024 - k] = fmaf(zn2, __ldg(gamma + 1024 - k), __ldg(beta + 1024 - k));
        if (k > 0)
            orow[1024 + k] = fmaf(zn2, __ldg(gamma + 1024 + k), __ldg(beta + 1024 + k));
    }
    if (u == 0) {
        float zn = fmaf(r[1].x, rs, cc);
        orow[512]  = fmaf(zn, __ldg(gamma + 512),  __ldg(beta + 512));
        orow[1536] = fmaf(zn, __ldg(gamma + 1536), __ldg(beta + 1536));
    }
}

// ---------------------------------------------------------------- launch
extern "C" void kernel_launch(void* const* d_in, const int* in_sizes, int n_in,
                              void* d_out, int out_size) {
    const float* x     = (const float*)d_in[0];
    const float* gamma = (const float*)d_in[1];
    const float* beta  = (const float*)d_in[2];
    float* out = (float*)d_out;

    fft_ln_kernel<<<ROWS / 4, 128>>>(x, gamma, beta, out);
}